// round 3
// baseline (speedup 1.0000x reference)
#include <cuda_runtime.h>
#include <cstdint>
#include <math.h>

#define NPTS 1000000
#define NC   64
#define NS   16
#define SCALE_XYZ 8388608    // 512*512*32
#define SCALE_YZ  16384      // 512*32
#define SCALE_Z   32
#define TOTAL_CELLS 33554432 // 4 * SCALE_XYZ
#define NBLK_SCAN 2048       // TOTAL_CELLS bytes / (256 thr * 64 B)

// ---------------- scratch (device globals; no allocation allowed) -------------
__device__ unsigned char g_flag[TOTAL_CELLS];  // occupancy bytes (memset 0)
__device__ int   g_rank[TOTAL_CELLS];          // rank at occupied cells ONLY (no memset needed)
__device__ int   g_code[NPTS];
__device__ int   g_inv[NPTS];
__device__ int   g_unq[NPTS];                  // memset 0xFF => -1 padding
__device__ int   g_ref[NPTS];                  // memset 0x7F => big for atomicMin
__device__ float g_cnt[NPTS];
__device__ int   g_bsum[NBLK_SCAN];

// ---------------- stage 1: voxel code + occupancy flag ----------------------
__global__ void k_code(const float* __restrict__ mu, const int* __restrict__ bidx, int n) {
    int i = blockIdx.x * blockDim.x + threadIdx.x;
    if (i >= n) return;
    float x = mu[i*3+0], y = mu[i*3+1], z = mu[i*3+2];
    // must match XLA exactly: (mu - pc_min) / vox with IEEE div, floor, int32 cast
    int ix = (int)floorf(__fdiv_rn(x - (-51.2f), 0.2f));
    int iy = (int)floorf(__fdiv_rn(y - (-51.2f), 0.2f));
    int iz = (int)floorf(__fdiv_rn(z - (-3.2f),  0.2f));
    int code = bidx[i] * SCALE_XYZ + iz * SCALE_YZ + iy * SCALE_Z + ix;
    g_code[i] = code;
    g_flag[code] = 1;
}

__device__ __forceinline__ int sum16(uint4 v) {
    int s = 0;
    s = __dp4a((int)v.x, (int)0x01010101, s);
    s = __dp4a((int)v.y, (int)0x01010101, s);
    s = __dp4a((int)v.z, (int)0x01010101, s);
    s = __dp4a((int)v.w, (int)0x01010101, s);
    return s;
}

// ---------------- stage 2a: per-block flag sums (64 bytes / thread) ----------
__global__ void k_pass1() {
    const uint4* p = (const uint4*)g_flag;
    int tbase = blockIdx.x * 1024 + threadIdx.x * 4;  // 4 consecutive uint4 / thread
    int s = 0;
    #pragma unroll
    for (int j = 0; j < 4; j++) s += sum16(p[tbase + j]);
    __shared__ int sh[256];
    sh[threadIdx.x] = s; __syncthreads();
    for (int o = 128; o > 0; o >>= 1) {
        if (threadIdx.x < o) sh[threadIdx.x] += sh[threadIdx.x + o];
        __syncthreads();
    }
    if (threadIdx.x == 0) g_bsum[blockIdx.x] = sh[0];
}

// ---------------- stage 2b: single-block scan of 2048 block sums -------------
__global__ void k_scanb() {
    __shared__ int sh[1024];
    int t = threadIdx.x;
    int v0 = g_bsum[t*2], v1 = g_bsum[t*2+1];
    sh[t] = v0 + v1; __syncthreads();
    for (int o = 1; o < 1024; o <<= 1) {
        int val = (t >= o) ? sh[t - o] : 0;
        __syncthreads();
        sh[t] += val;
        __syncthreads();
    }
    int excl = (t == 0) ? 0 : sh[t - 1];
    g_bsum[t*2] = excl;
    g_bsum[t*2+1] = excl + v0;
}

// ---------------- stage 2c: ranks at occupied cells + sorted unique codes ----
__global__ void k_pass3() {
    __shared__ int sh[256];
    const uint4* p = (const uint4*)g_flag;
    int t = threadIdx.x;
    int tbase = blockIdx.x * 1024 + t * 4;
    uint4 v[4]; int s = 0;
    #pragma unroll
    for (int j = 0; j < 4; j++) { v[j] = p[tbase + j]; s += sum16(v[j]); }
    sh[t] = s; __syncthreads();
    for (int o = 1; o < 256; o <<= 1) {
        int val = (t >= o) ? sh[t - o] : 0;
        __syncthreads();
        sh[t] += val;
        __syncthreads();
    }
    int run = g_bsum[blockIdx.x] + ((t == 0) ? 0 : sh[t - 1]);
    int cell = tbase * 16;
    #pragma unroll
    for (int j = 0; j < 4; j++) {
        unsigned int w[4] = { v[j].x, v[j].y, v[j].z, v[j].w };
        #pragma unroll
        for (int q = 0; q < 4; q++) {
            if (w[q]) {  // skip empty words (97% of cells)
                #pragma unroll
                for (int b = 0; b < 4; b++) {
                    if ((w[q] >> (b*8)) & 1) {
                        int c = cell + q*4 + b;
                        g_rank[c] = run;
                        g_unq[run] = c;
                        run++;
                    }
                }
            }
        }
        cell += 16;
    }
}

// ---------------- stage 3: inverse index + first-occurrence ref --------------
__global__ void k_inv(int n) {
    int i = blockIdx.x * blockDim.x + threadIdx.x;
    if (i >= n) return;
    int s = g_rank[g_code[i]];   // only occupied cells are ever read
    g_inv[i] = s;
    atomicMin(&g_ref[s], i);
}

// ---------------- stage 4: warp-per-point atomic accumulate ------------------
__global__ void k_accum(const float* __restrict__ mu, const float* __restrict__ sc,
                        const float* __restrict__ rot, const float* __restrict__ ft,
                        const float* __restrict__ sm, float* __restrict__ out, int n) {
    int gtid = blockIdx.x * blockDim.x + threadIdx.x;
    int i = gtid >> 5;
    int lane = gtid & 31;
    if (i >= n) return;
    int s = g_inv[i];

    float* out_mu  = out;
    float* out_sc  = out + 3  * (size_t)n;
    float* out_rot = out + 6  * (size_t)n;
    float* out_ft  = out + 10 * (size_t)n;
    float* out_sm  = out + 74 * (size_t)n;

    // features: every lane handles 2 channels
    atomicAdd(&out_ft[(size_t)s*NC + lane],      ft[(size_t)i*NC + lane]);
    atomicAdd(&out_ft[(size_t)s*NC + lane + 32], ft[(size_t)i*NC + lane + 32]);

    if (lane < 3) {
        atomicAdd(&out_mu[s*3 + lane], mu[i*3 + lane]);
    } else if (lane < 6) {
        atomicAdd(&out_sc[s*3 + (lane-3)], sc[i*3 + (lane-3)]);
    } else if (lane < 10) {
        int k = lane - 6;
        int r = g_ref[s];
        float d = rot[i*4+0]*rot[r*4+0] + rot[i*4+1]*rot[r*4+1]
                + rot[i*4+2]*rot[r*4+2] + rot[i*4+3]*rot[r*4+3];
        float sg = (d + 1e-8f) >= 0.0f ? 1.0f : -1.0f;
        atomicAdd(&out_rot[s*4 + k], rot[i*4 + k] * sg);
    } else if (lane == 10) {
        atomicAdd(&g_cnt[s], 1.0f);
    } else if (lane < 27) {
        int k = lane - 11;
        atomicAdd(&out_sm[(size_t)s*NS + k], sm[(size_t)i*NS + k]);
    }
}

// ---------------- stage 5: warp-per-row finalize -----------------------------
__global__ void k_final(float* __restrict__ out, int n) {
    int gtid = blockIdx.x * blockDim.x + threadIdx.x;
    int r = gtid >> 5;
    int lane = gtid & 31;
    if (r >= n) return;

    float* out_mu  = out;
    float* out_sc  = out + 3  * (size_t)n;
    float* out_rot = out + 6  * (size_t)n;
    float* out_ft  = out + 10 * (size_t)n;
    float* out_sm  = out + 74 * (size_t)n;
    float* out_vx  = out + 90 * (size_t)n;

    float c = g_cnt[r];
    float denom = fmaxf(c, 1.0f);
    float inv_d = 1.0f / denom;

    out_ft[(size_t)r*NC + lane]      *= inv_d;
    out_ft[(size_t)r*NC + lane + 32] *= inv_d;

    if (lane < 3) {
        out_mu[r*3 + lane] *= inv_d;
    } else if (lane < 6) {
        out_sc[r*3 + (lane-3)] *= inv_d;
    } else if (lane < 10) {
        int k = lane - 6;
        float p0 = out_rot[r*4+0] * inv_d;
        float p1 = out_rot[r*4+1] * inv_d;
        float p2 = out_rot[r*4+2] * inv_d;
        float p3 = out_rot[r*4+3] * inv_d;
        float nrm = sqrtf(p0*p0 + p1*p1 + p2*p2 + p3*p3);
        float dv = fmaxf(nrm, 1e-12f);
        float pk = (k == 0) ? p0 : (k == 1) ? p1 : (k == 2) ? p2 : p3;
        out_rot[r*4 + k] = pk / dv;
    } else if (lane == 10) {
        // intentionally empty — lane 10 was the count lane in k_accum.
    } else if (lane < 27) {
        int k = lane - 11;
        out_sm[(size_t)r*NS + k] *= inv_d;
    } else if (lane == 27) {
        int u = g_unq[r];
        int vb, vz, vy, vx;
        if (u < 0) { vb = -1; vz = 511; vy = 511; vx = 31; }  // jnp floor-div/mod of -1
        else {
            vb = u / SCALE_XYZ; int rem = u % SCALE_XYZ;
            vz = rem / SCALE_YZ; rem %= SCALE_YZ;
            vy = rem / SCALE_Z;  vx = rem % SCALE_Z;
        }
        float* vo = out_vx + (size_t)r * 4;
        vo[0] = (float)vb; vo[1] = (float)vz; vo[2] = (float)vy; vo[3] = (float)vx;
    }
}

// -----------------------------------------------------------------------------
extern "C" void kernel_launch(void* const* d_in, const int* in_sizes, int n_in,
                              void* d_out, int out_size) {
    const float* mu   = (const float*)d_in[0];
    const float* sc   = (const float*)d_in[1];
    const float* rot  = (const float*)d_in[2];
    const float* ft   = (const float*)d_in[3];
    const float* sm   = (const float*)d_in[4];
    const int*   bidx = (const int*)  d_in[5];
    float* out = (float*)d_out;
    int n = in_sizes[5];   // batch_idx element count == N

    void *p_flag, *p_unq, *p_ref, *p_cnt;
    cudaGetSymbolAddress(&p_flag, g_flag);
    cudaGetSymbolAddress(&p_unq, g_unq);
    cudaGetSymbolAddress(&p_ref, g_ref);
    cudaGetSymbolAddress(&p_cnt, g_cnt);

    cudaMemsetAsync(p_flag, 0x00, (size_t)TOTAL_CELLS);           // byte flags
    cudaMemsetAsync(p_unq, 0xFF, (size_t)n * sizeof(int));        // -1 padding
    cudaMemsetAsync(p_ref, 0x7F, (size_t)n * sizeof(int));        // big for atomicMin
    cudaMemsetAsync(p_cnt, 0x00, (size_t)n * sizeof(float));
    cudaMemsetAsync(out,   0x00, 90 * (size_t)n * sizeof(float)); // sum regions

    int tb = 256;
    k_code <<<(n + tb - 1) / tb, tb>>>(mu, bidx, n);
    k_pass1<<<NBLK_SCAN, tb>>>();
    k_scanb<<<1, 1024>>>();
    k_pass3<<<NBLK_SCAN, tb>>>();
    k_inv  <<<(n + tb - 1) / tb, tb>>>(n);

    long long wthreads = (long long)n * 32;
    int wblocks = (int)((wthreads + tb - 1) / tb);
    k_accum<<<wblocks, tb>>>(mu, sc, rot, ft, sm, out, n);
    k_final<<<wblocks, tb>>>(out, n);
}

// round 4
// speedup vs baseline: 1.5179x; 1.5179x over previous
#include <cuda_runtime.h>
#include <cstdint>
#include <math.h>
#include <limits.h>

#define NPTS 1000000
#define NC   64
#define NS   16
#define SCALE_XYZ 8388608    // 512*512*32
#define SCALE_YZ  16384      // 512*32
#define SCALE_Z   32
#define TOTAL_CELLS 33554432 // 4 * SCALE_XYZ
#define NBLK_SCAN 2048       // TOTAL_CELLS bytes / (256 thr * 64 B)
#define NBLK_CSCAN 1024      // >= ceil(NPTS/1024)

// ---------------- scratch (device globals; no allocation allowed) -------------
__device__ unsigned char g_flag[TOTAL_CELLS];  // occupancy bytes (memset 0)
__device__ int   g_rank[TOTAL_CELLS];          // rank at occupied cells ONLY (no memset)
__device__ int   g_code[NPTS];
__device__ int   g_inv[NPTS];
__device__ int   g_unq[NPTS];                  // memset 0xFF => -1 padding
__device__ int   g_icnt[NPTS];                 // per-segment point counts (memset 0)
__device__ int   g_off[NPTS + 1];              // CSR offsets (exclusive scan)
__device__ int   g_cur[NPTS];                  // scatter cursors (copy of g_off)
__device__ int   g_pts[NPTS];                  // points grouped by segment
__device__ int   g_bsum[NBLK_SCAN];
__device__ int   g_bsum2[NBLK_CSCAN];

// ---------------- stage 1: voxel code + occupancy flag ----------------------
__global__ void k_code(const float* __restrict__ mu, const int* __restrict__ bidx, int n) {
    int i = blockIdx.x * blockDim.x + threadIdx.x;
    if (i >= n) return;
    float x = mu[i*3+0], y = mu[i*3+1], z = mu[i*3+2];
    // must match XLA exactly: (mu - pc_min) / vox with IEEE div, floor, int32 cast
    int ix = (int)floorf(__fdiv_rn(x - (-51.2f), 0.2f));
    int iy = (int)floorf(__fdiv_rn(y - (-51.2f), 0.2f));
    int iz = (int)floorf(__fdiv_rn(z - (-3.2f),  0.2f));
    int code = bidx[i] * SCALE_XYZ + iz * SCALE_YZ + iy * SCALE_Z + ix;
    g_code[i] = code;
    g_flag[code] = 1;
}

__device__ __forceinline__ int sum16(uint4 v) {
    int s = 0;
    s = __dp4a((int)v.x, (int)0x01010101, s);
    s = __dp4a((int)v.y, (int)0x01010101, s);
    s = __dp4a((int)v.z, (int)0x01010101, s);
    s = __dp4a((int)v.w, (int)0x01010101, s);
    return s;
}

// ---------------- stage 2a: per-block flag sums (64 bytes / thread) ----------
__global__ void k_pass1() {
    const uint4* p = (const uint4*)g_flag;
    int tbase = blockIdx.x * 1024 + threadIdx.x * 4;
    int s = 0;
    #pragma unroll
    for (int j = 0; j < 4; j++) s += sum16(p[tbase + j]);
    __shared__ int sh[256];
    sh[threadIdx.x] = s; __syncthreads();
    for (int o = 128; o > 0; o >>= 1) {
        if (threadIdx.x < o) sh[threadIdx.x] += sh[threadIdx.x + o];
        __syncthreads();
    }
    if (threadIdx.x == 0) g_bsum[blockIdx.x] = sh[0];
}

// ---------------- stage 2b: single-block scan of 2048 block sums -------------
__global__ void k_scanb() {
    __shared__ int sh[1024];
    int t = threadIdx.x;
    int v0 = g_bsum[t*2], v1 = g_bsum[t*2+1];
    sh[t] = v0 + v1; __syncthreads();
    for (int o = 1; o < 1024; o <<= 1) {
        int val = (t >= o) ? sh[t - o] : 0;
        __syncthreads();
        sh[t] += val;
        __syncthreads();
    }
    int excl = (t == 0) ? 0 : sh[t - 1];
    g_bsum[t*2] = excl;
    g_bsum[t*2+1] = excl + v0;
}

// ---------------- stage 2c: ranks at occupied cells + sorted unique codes ----
__global__ void k_pass3() {
    __shared__ int sh[256];
    const uint4* p = (const uint4*)g_flag;
    int t = threadIdx.x;
    int tbase = blockIdx.x * 1024 + t * 4;
    uint4 v[4]; int s = 0;
    #pragma unroll
    for (int j = 0; j < 4; j++) { v[j] = p[tbase + j]; s += sum16(v[j]); }
    sh[t] = s; __syncthreads();
    for (int o = 1; o < 256; o <<= 1) {
        int val = (t >= o) ? sh[t - o] : 0;
        __syncthreads();
        sh[t] += val;
        __syncthreads();
    }
    int run = g_bsum[blockIdx.x] + ((t == 0) ? 0 : sh[t - 1]);
    int cell = tbase * 16;
    #pragma unroll
    for (int j = 0; j < 4; j++) {
        unsigned int w[4] = { v[j].x, v[j].y, v[j].z, v[j].w };
        #pragma unroll
        for (int q = 0; q < 4; q++) {
            if (w[q]) {
                #pragma unroll
                for (int b = 0; b < 4; b++) {
                    if ((w[q] >> (b*8)) & 1) {
                        int c = cell + q*4 + b;
                        g_rank[c] = run;
                        g_unq[run] = c;
                        run++;
                    }
                }
            }
        }
        cell += 16;
    }
}

// ---------------- stage 3: inverse index + segment counts --------------------
__global__ void k_inv(int n) {
    int i = blockIdx.x * blockDim.x + threadIdx.x;
    if (i >= n) return;
    int s = g_rank[g_code[i]];
    g_inv[i] = s;
    atomicAdd(&g_icnt[s], 1);
}

// ---------------- stage 3b: scan counts (3 sub-kernels) ----------------------
__global__ void k_cs1(int n) {
    int t = threadIdx.x;
    int base = blockIdx.x * 1024 + t * 4;
    int s = 0;
    if (base < n) {   // n % 4 == 0 so int4 load is safe when base < n
        int4 v = *(const int4*)&g_icnt[base];
        s = v.x + v.y + v.z + v.w;
    }
    __shared__ int sh[256];
    sh[t] = s; __syncthreads();
    for (int o = 128; o > 0; o >>= 1) {
        if (t < o) sh[t] += sh[t + o];
        __syncthreads();
    }
    if (t == 0) g_bsum2[blockIdx.x] = sh[0];
}

__global__ void k_cs2(int nblk) {
    __shared__ int sh[NBLK_CSCAN];
    int t = threadIdx.x;
    int v = (t < nblk) ? g_bsum2[t] : 0;
    sh[t] = v; __syncthreads();
    for (int o = 1; o < NBLK_CSCAN; o <<= 1) {
        int val = (t >= o) ? sh[t - o] : 0;
        __syncthreads();
        sh[t] += val;
        __syncthreads();
    }
    g_bsum2[t] = (t == 0) ? 0 : sh[t - 1];   // exclusive
}

__global__ void k_cs3(int n) {
    __shared__ int sh[256];
    int t = threadIdx.x;
    int base = blockIdx.x * 1024 + t * 4;
    int4 v = make_int4(0, 0, 0, 0);
    if (base < n) v = *(const int4*)&g_icnt[base];
    int s = v.x + v.y + v.z + v.w;
    sh[t] = s; __syncthreads();
    for (int o = 1; o < 256; o <<= 1) {
        int val = (t >= o) ? sh[t - o] : 0;
        __syncthreads();
        sh[t] += val;
        __syncthreads();
    }
    int run = g_bsum2[blockIdx.x] + ((t == 0) ? 0 : sh[t - 1]);
    if (base < n) {
        int e[4] = { v.x, v.y, v.z, v.w };
        #pragma unroll
        for (int j = 0; j < 4; j++) {
            g_off[base + j] = run;
            g_cur[base + j] = run;
            run += e[j];
            if (base + j == n - 1) g_off[n] = run;
        }
    }
}

// ---------------- stage 3c: scatter points into segment lists ----------------
__global__ void k_scatter(int n) {
    int i = blockIdx.x * blockDim.x + threadIdx.x;
    if (i >= n) return;
    int s = g_inv[i];
    int pos = atomicAdd(&g_cur[s], 1);
    g_pts[pos] = i;
}

// ---------------- stage 4: warp-per-row gather reduce + write ----------------
// lane map: 0-2 mu | 4-7 rot | 8-10 scale | 11-26 sem | 27 vox | all: ft 2ch
__global__ void k_reduce(const float* __restrict__ mu, const float* __restrict__ sc,
                         const float* __restrict__ rot, const float* __restrict__ ft,
                         const float* __restrict__ sm, float* __restrict__ out, int n) {
    int gtid = blockIdx.x * blockDim.x + threadIdx.x;
    int r = gtid >> 5;
    int lane = gtid & 31;
    if (r >= n) return;

    int start = g_off[r];
    int end   = g_off[r + 1];
    int c     = end - start;

    // first-occurrence reference index = min point index in segment
    int mn = INT_MAX;
    for (int j = start + lane; j < end; j += 32) mn = min(mn, g_pts[j]);
    int ref = __reduce_min_sync(0xffffffffu, mn);

    float q0 = 0.f, q1 = 0.f, q2 = 0.f, q3 = 0.f;
    if (c > 0) {
        q0 = __ldg(&rot[(size_t)ref*4+0]); q1 = __ldg(&rot[(size_t)ref*4+1]);
        q2 = __ldg(&rot[(size_t)ref*4+2]); q3 = __ldg(&rot[(size_t)ref*4+3]);
    }

    float a0 = 0.f, a1 = 0.f;   // ft channels lane, lane+32
    float am = 0.f;             // lane-specific small field

    for (int j = start; j < end; j++) {
        int i = g_pts[j];                     // broadcast load
        a0 += ft[(size_t)i*NC + lane];
        a1 += ft[(size_t)i*NC + lane + 32];
        if (lane < 3) {
            am += mu[(size_t)i*3 + lane];
        } else if (lane >= 4 && lane < 8) {
            float r0 = rot[(size_t)i*4+0], r1 = rot[(size_t)i*4+1];
            float r2 = rot[(size_t)i*4+2], r3 = rot[(size_t)i*4+3];
            float d = r0*q0 + r1*q1 + r2*q2 + r3*q3;
            float sg = (d + 1e-8f) >= 0.0f ? 1.0f : -1.0f;
            float rk = (lane == 4) ? r0 : (lane == 5) ? r1 : (lane == 6) ? r2 : r3;
            am += rk * sg;
        } else if (lane >= 8 && lane < 11) {
            am += sc[(size_t)i*3 + (lane - 8)];
        } else if (lane >= 11 && lane < 27) {
            am += sm[(size_t)i*NS + (lane - 11)];
        }
    }

    float inv_d = 1.0f / fmaxf((float)c, 1.0f);

    float* out_mu  = out;
    float* out_sc  = out + 3  * (size_t)n;
    float* out_rot = out + 6  * (size_t)n;
    float* out_ft  = out + 10 * (size_t)n;
    float* out_sm  = out + 74 * (size_t)n;
    float* out_vx  = out + 90 * (size_t)n;

    out_ft[(size_t)r*NC + lane]      = a0 * inv_d;
    out_ft[(size_t)r*NC + lane + 32] = a1 * inv_d;

    if (lane < 3) {
        out_mu[(size_t)r*3 + lane] = am * inv_d;
    } else if (lane >= 4 && lane < 8) {
        float p = am * inv_d;
        float v = p * p;                      // lanes 4-7 form an aligned quad
        v += __shfl_xor_sync(0x000000F0u, v, 1);
        v += __shfl_xor_sync(0x000000F0u, v, 2);
        float nrm = sqrtf(v);
        out_rot[(size_t)r*4 + (lane - 4)] = p / fmaxf(nrm, 1e-12f);
    } else if (lane >= 8 && lane < 11) {
        out_sc[(size_t)r*3 + (lane - 8)] = am * inv_d;
    } else if (lane >= 11 && lane < 27) {
        out_sm[(size_t)r*NS + (lane - 11)] = am * inv_d;
    } else if (lane == 27) {
        int u = g_unq[r];
        int vb, vz, vy, vx;
        if (u < 0) { vb = -1; vz = 511; vy = 511; vx = 31; }  // jnp floor-div/mod of -1
        else {
            vb = u / SCALE_XYZ; int rem = u % SCALE_XYZ;
            vz = rem / SCALE_YZ; rem %= SCALE_YZ;
            vy = rem / SCALE_Z;  vx = rem % SCALE_Z;
        }
        float* vo = out_vx + (size_t)r * 4;
        vo[0] = (float)vb; vo[1] = (float)vz; vo[2] = (float)vy; vo[3] = (float)vx;
    }
}

// -----------------------------------------------------------------------------
extern "C" void kernel_launch(void* const* d_in, const int* in_sizes, int n_in,
                              void* d_out, int out_size) {
    const float* mu   = (const float*)d_in[0];
    const float* sc   = (const float*)d_in[1];
    const float* rot  = (const float*)d_in[2];
    const float* ft   = (const float*)d_in[3];
    const float* sm   = (const float*)d_in[4];
    const int*   bidx = (const int*)  d_in[5];
    float* out = (float*)d_out;
    int n = in_sizes[5];   // batch_idx element count == N

    void *p_flag, *p_unq, *p_icnt;
    cudaGetSymbolAddress(&p_flag, g_flag);
    cudaGetSymbolAddress(&p_unq, g_unq);
    cudaGetSymbolAddress(&p_icnt, g_icnt);

    cudaMemsetAsync(p_flag, 0x00, (size_t)TOTAL_CELLS);      // byte flags
    cudaMemsetAsync(p_unq,  0xFF, (size_t)n * sizeof(int));  // -1 padding
    cudaMemsetAsync(p_icnt, 0x00, (size_t)n * sizeof(int));  // counts

    int tb = 256;
    int pblk = (n + tb - 1) / tb;
    int cblk = (n + 1023) / 1024;

    k_code   <<<pblk, tb>>>(mu, bidx, n);
    k_pass1  <<<NBLK_SCAN, tb>>>();
    k_scanb  <<<1, 1024>>>();
    k_pass3  <<<NBLK_SCAN, tb>>>();
    k_inv    <<<pblk, tb>>>(n);
    k_cs1    <<<cblk, tb>>>(n);
    k_cs2    <<<1, NBLK_CSCAN>>>(cblk);
    k_cs3    <<<cblk, tb>>>(n);
    k_scatter<<<pblk, tb>>>(n);

    long long wthreads = (long long)n * 32;
    int wblocks = (int)((wthreads + tb - 1) / tb);
    k_reduce <<<wblocks, tb>>>(mu, sc, rot, ft, sm, out, n);
}

// round 5
// speedup vs baseline: 2.0236x; 1.3332x over previous
#include <cuda_runtime.h>
#include <cstdint>
#include <math.h>
#include <limits.h>

#define NPTS 1000000
#define NC   64
#define NS   16
#define SCALE_XYZ 8388608    // 512*512*32
#define SCALE_YZ  16384      // 512*32
#define SCALE_Z   32
#define TOTAL_CELLS 33554432 // 4 * SCALE_XYZ
#define NBLK_SCAN 2048       // TOTAL_CELLS bytes / (256 thr * 64 B)
#define NBLK_CSCAN 1024      // >= ceil(NPTS/1024)

// ---------------- scratch (device globals; no allocation allowed) -------------
__device__ unsigned char g_flag[TOTAL_CELLS];  // occupancy bytes (memset 0)
__device__ int   g_rank[TOTAL_CELLS];          // rank at occupied cells ONLY (no memset)
__device__ int   g_code[NPTS];
__device__ int   g_inv[NPTS];
__device__ int   g_unq[NPTS];                  // memset 0xFF => -1 padding
__device__ int   g_icnt[NPTS];                 // per-segment point counts (memset 0)
__device__ int   g_off[NPTS + 1];              // CSR offsets (exclusive scan)
__device__ int   g_cur[NPTS];                  // scatter cursors (copy of g_off)
__device__ int   g_pts[NPTS];                  // points grouped by segment
__device__ int   g_bsum[NBLK_SCAN];
__device__ int   g_bsum2[NBLK_CSCAN];

// ---------------- stage 1: voxel code + occupancy flag ----------------------
__global__ void k_code(const float* __restrict__ mu, const int* __restrict__ bidx, int n) {
    int i = blockIdx.x * blockDim.x + threadIdx.x;
    if (i >= n) return;
    float x = mu[i*3+0], y = mu[i*3+1], z = mu[i*3+2];
    // must match XLA exactly: (mu - pc_min) / vox with IEEE div, floor, int32 cast
    int ix = (int)floorf(__fdiv_rn(x - (-51.2f), 0.2f));
    int iy = (int)floorf(__fdiv_rn(y - (-51.2f), 0.2f));
    int iz = (int)floorf(__fdiv_rn(z - (-3.2f),  0.2f));
    int code = bidx[i] * SCALE_XYZ + iz * SCALE_YZ + iy * SCALE_Z + ix;
    g_code[i] = code;
    g_flag[code] = 1;
}

__device__ __forceinline__ int sum16(uint4 v) {
    int s = 0;
    s = __dp4a((int)v.x, (int)0x01010101, s);
    s = __dp4a((int)v.y, (int)0x01010101, s);
    s = __dp4a((int)v.z, (int)0x01010101, s);
    s = __dp4a((int)v.w, (int)0x01010101, s);
    return s;
}

// ---------------- stage 2a: per-block flag sums (64 bytes / thread) ----------
__global__ void k_pass1() {
    const uint4* p = (const uint4*)g_flag;
    int tbase = blockIdx.x * 1024 + threadIdx.x * 4;
    int s = 0;
    #pragma unroll
    for (int j = 0; j < 4; j++) s += sum16(p[tbase + j]);
    __shared__ int sh[256];
    sh[threadIdx.x] = s; __syncthreads();
    for (int o = 128; o > 0; o >>= 1) {
        if (threadIdx.x < o) sh[threadIdx.x] += sh[threadIdx.x + o];
        __syncthreads();
    }
    if (threadIdx.x == 0) g_bsum[blockIdx.x] = sh[0];
}

// ---------------- stage 2b: single-block scan of 2048 block sums -------------
__global__ void k_scanb() {
    __shared__ int sh[1024];
    int t = threadIdx.x;
    int v0 = g_bsum[t*2], v1 = g_bsum[t*2+1];
    sh[t] = v0 + v1; __syncthreads();
    for (int o = 1; o < 1024; o <<= 1) {
        int val = (t >= o) ? sh[t - o] : 0;
        __syncthreads();
        sh[t] += val;
        __syncthreads();
    }
    int excl = (t == 0) ? 0 : sh[t - 1];
    g_bsum[t*2] = excl;
    g_bsum[t*2+1] = excl + v0;
}

// ---------------- stage 2c: ranks at occupied cells + sorted unique codes ----
__global__ void k_pass3() {
    __shared__ int sh[256];
    const uint4* p = (const uint4*)g_flag;
    int t = threadIdx.x;
    int tbase = blockIdx.x * 1024 + t * 4;
    uint4 v[4]; int s = 0;
    #pragma unroll
    for (int j = 0; j < 4; j++) { v[j] = p[tbase + j]; s += sum16(v[j]); }
    sh[t] = s; __syncthreads();
    for (int o = 1; o < 256; o <<= 1) {
        int val = (t >= o) ? sh[t - o] : 0;
        __syncthreads();
        sh[t] += val;
        __syncthreads();
    }
    int run = g_bsum[blockIdx.x] + ((t == 0) ? 0 : sh[t - 1]);
    int cell = tbase * 16;
    #pragma unroll
    for (int j = 0; j < 4; j++) {
        unsigned int w[4] = { v[j].x, v[j].y, v[j].z, v[j].w };
        #pragma unroll
        for (int q = 0; q < 4; q++) {
            if (w[q]) {
                #pragma unroll
                for (int b = 0; b < 4; b++) {
                    if ((w[q] >> (b*8)) & 1) {
                        int c = cell + q*4 + b;
                        g_rank[c] = run;
                        g_unq[run] = c;
                        run++;
                    }
                }
            }
        }
        cell += 16;
    }
}

// ---------------- stage 3: inverse index + segment counts --------------------
__global__ void k_inv(int n) {
    int i = blockIdx.x * blockDim.x + threadIdx.x;
    if (i >= n) return;
    int s = g_rank[g_code[i]];
    g_inv[i] = s;
    atomicAdd(&g_icnt[s], 1);
}

// ---------------- stage 3b: scan counts (3 sub-kernels) ----------------------
__global__ void k_cs1(int n) {
    int t = threadIdx.x;
    int base = blockIdx.x * 1024 + t * 4;
    int s = 0;
    if (base < n) {   // n % 4 == 0 so int4 load is safe when base < n
        int4 v = *(const int4*)&g_icnt[base];
        s = v.x + v.y + v.z + v.w;
    }
    __shared__ int sh[256];
    sh[t] = s; __syncthreads();
    for (int o = 128; o > 0; o >>= 1) {
        if (t < o) sh[t] += sh[t + o];
        __syncthreads();
    }
    if (t == 0) g_bsum2[blockIdx.x] = sh[0];
}

__global__ void k_cs2(int nblk) {
    __shared__ int sh[NBLK_CSCAN];
    int t = threadIdx.x;
    int v = (t < nblk) ? g_bsum2[t] : 0;
    sh[t] = v; __syncthreads();
    for (int o = 1; o < NBLK_CSCAN; o <<= 1) {
        int val = (t >= o) ? sh[t - o] : 0;
        __syncthreads();
        sh[t] += val;
        __syncthreads();
    }
    g_bsum2[t] = (t == 0) ? 0 : sh[t - 1];   // exclusive
}

__global__ void k_cs3(int n) {
    __shared__ int sh[256];
    int t = threadIdx.x;
    int base = blockIdx.x * 1024 + t * 4;
    int4 v = make_int4(0, 0, 0, 0);
    if (base < n) v = *(const int4*)&g_icnt[base];
    int s = v.x + v.y + v.z + v.w;
    sh[t] = s; __syncthreads();
    for (int o = 1; o < 256; o <<= 1) {
        int val = (t >= o) ? sh[t - o] : 0;
        __syncthreads();
        sh[t] += val;
        __syncthreads();
    }
    int run = g_bsum2[blockIdx.x] + ((t == 0) ? 0 : sh[t - 1]);
    if (base < n) {
        int e[4] = { v.x, v.y, v.z, v.w };
        #pragma unroll
        for (int j = 0; j < 4; j++) {
            g_off[base + j] = run;
            g_cur[base + j] = run;
            run += e[j];
            if (base + j == n - 1) g_off[n] = run;
        }
    }
}

// ---------------- stage 3c: scatter points into segment lists ----------------
__global__ void k_scatter(int n) {
    int i = blockIdx.x * blockDim.x + threadIdx.x;
    if (i >= n) return;
    int s = g_inv[i];
    int pos = atomicAdd(&g_cur[s], 1);
    g_pts[pos] = i;
}

// ---------------- stage 4: warp-per-row gather reduce + write ----------------
// lane map: 0-2 mu | 3 dummy(rot w) | 4-7 rot | 8-10 scale | 11-26 sem | 27 vox
// all lanes: ft channels (2*lane, 2*lane+1) via float2
__global__ void k_reduce(const float* __restrict__ mu, const float* __restrict__ sc,
                         const float* __restrict__ rot, const float* __restrict__ ft,
                         const float* __restrict__ sm, float* __restrict__ out, int n) {
    int gtid = blockIdx.x * blockDim.x + threadIdx.x;
    int r = gtid >> 5;
    int lane = gtid & 31;
    if (r >= n) return;

    int start = g_off[r];
    int end   = g_off[r + 1];
    int c     = end - start;

    // per-lane gather descriptor (uniform over loop)
    const float* gbase; int gstride, gsub;
    if (lane < 3)       { gbase = mu;  gstride = 3;  gsub = lane; }
    else if (lane < 8)  { gbase = rot; gstride = 4;  gsub = (lane - 4) & 3; } // lane 3 -> rot comp 3 (unused)
    else if (lane < 11) { gbase = sc;  gstride = 3;  gsub = lane - 8; }
    else if (lane < 27) { gbase = sm;  gstride = 16; gsub = lane - 11; }
    else                { gbase = mu;  gstride = 0;  gsub = 0; }             // dummy
    bool isrot = (lane >= 4 && lane < 8);

    const float2* ft2 = (const float2*)ft;
    float a0 = 0.f, a1 = 0.f, am = 0.f;

    if (c == 1) {
        // singleton fast path: ref = self, dot = |q|^2 >= 0 -> sign always +1
        int i = g_pts[start];
        float2 f = __ldg(&ft2[(size_t)i*32 + lane]);
        a0 = f.x; a1 = f.y;
        am = __ldg(&gbase[(size_t)i*gstride + gsub]);
    } else if (c > 1) {
        // first-occurrence reference = min point index
        int mn = INT_MAX;
        for (int j = start + lane; j < end; j += 32) mn = min(mn, g_pts[j]);
        mn = __reduce_min_sync(0xffffffffu, mn);
        // this rot lane's reference component
        float qc = 0.f;
        if (isrot) qc = __ldg(&rot[(size_t)mn*4 + (lane - 4)]);
        for (int j = start; j < end; j++) {
            int i = g_pts[j];                                  // broadcast load
            float2 f = __ldg(&ft2[(size_t)i*32 + lane]);
            a0 += f.x; a1 += f.y;
            float v = __ldg(&gbase[(size_t)i*gstride + gsub]); // one converged gather
            if (isrot) {
                float p = v * qc;                              // partial dot
                p += __shfl_xor_sync(0x000000F0u, p, 1);
                p += __shfl_xor_sync(0x000000F0u, p, 2);       // full dot in quad
                float sg = (p + 1e-8f) >= 0.f ? 1.f : -1.f;
                v *= sg;
            }
            am += v;
        }
    }
    // c == 0: padded segment, all zeros

    float inv_d = 1.0f / fmaxf((float)c, 1.0f);

    float*  out_mu  = out;
    float*  out_sc  = out + 3  * (size_t)n;
    float*  out_rot = out + 6  * (size_t)n;
    float2* out_ft2 = (float2*)(out + 10 * (size_t)n);
    float*  out_sm  = out + 74 * (size_t)n;
    float*  out_vx  = out + 90 * (size_t)n;

    out_ft2[(size_t)r*32 + lane] = make_float2(a0 * inv_d, a1 * inv_d);

    if (lane < 3) {
        out_mu[(size_t)r*3 + lane] = am * inv_d;
    } else if (isrot) {
        float p = am * inv_d;
        float v = p * p;
        v += __shfl_xor_sync(0x000000F0u, v, 1);
        v += __shfl_xor_sync(0x000000F0u, v, 2);
        float nrm = sqrtf(v);
        out_rot[(size_t)r*4 + (lane - 4)] = p / fmaxf(nrm, 1e-12f);
    } else if (lane >= 8 && lane < 11) {
        out_sc[(size_t)r*3 + (lane - 8)] = am * inv_d;
    } else if (lane >= 11 && lane < 27) {
        out_sm[(size_t)r*NS + (lane - 11)] = am * inv_d;
    } else if (lane == 27) {
        int u = g_unq[r];
        int vb, vz, vy, vx;
        if (u < 0) { vb = -1; vz = 511; vy = 511; vx = 31; }  // jnp floor-div/mod of -1
        else {
            vb = u / SCALE_XYZ; int rem = u % SCALE_XYZ;
            vz = rem / SCALE_YZ; rem %= SCALE_YZ;
            vy = rem / SCALE_Z;  vx = rem % SCALE_Z;
        }
        float* vo = out_vx + (size_t)r * 4;
        vo[0] = (float)vb; vo[1] = (float)vz; vo[2] = (float)vy; vo[3] = (float)vx;
    }
}

// -----------------------------------------------------------------------------
extern "C" void kernel_launch(void* const* d_in, const int* in_sizes, int n_in,
                              void* d_out, int out_size) {
    const float* mu   = (const float*)d_in[0];
    const float* sc   = (const float*)d_in[1];
    const float* rot  = (const float*)d_in[2];
    const float* ft   = (const float*)d_in[3];
    const float* sm   = (const float*)d_in[4];
    const int*   bidx = (const int*)  d_in[5];
    float* out = (float*)d_out;
    int n = in_sizes[5];   // batch_idx element count == N

    void *p_flag, *p_unq, *p_icnt;
    cudaGetSymbolAddress(&p_flag, g_flag);
    cudaGetSymbolAddress(&p_unq, g_unq);
    cudaGetSymbolAddress(&p_icnt, g_icnt);

    cudaMemsetAsync(p_flag, 0x00, (size_t)TOTAL_CELLS);      // byte flags
    cudaMemsetAsync(p_unq,  0xFF, (size_t)n * sizeof(int));  // -1 padding
    cudaMemsetAsync(p_icnt, 0x00, (size_t)n * sizeof(int));  // counts

    int tb = 256;
    int pblk = (n + tb - 1) / tb;
    int cblk = (n + 1023) / 1024;

    k_code   <<<pblk, tb>>>(mu, bidx, n);
    k_pass1  <<<NBLK_SCAN, tb>>>();
    k_scanb  <<<1, 1024>>>();
    k_pass3  <<<NBLK_SCAN, tb>>>();
    k_inv    <<<pblk, tb>>>(n);
    k_cs1    <<<cblk, tb>>>(n);
    k_cs2    <<<1, NBLK_CSCAN>>>(cblk);
    k_cs3    <<<cblk, tb>>>(n);
    k_scatter<<<pblk, tb>>>(n);

    long long wthreads = (long long)n * 32;
    int wblocks = (int)((wthreads + tb - 1) / tb);
    k_reduce <<<wblocks, tb>>>(mu, sc, rot, ft, sm, out, n);
}

// round 6
// speedup vs baseline: 2.1554x; 1.0651x over previous
#include <cuda_runtime.h>
#include <cstdint>
#include <math.h>
#include <limits.h>

#define NPTS 1000000
#define NC   64
#define NS   16
#define SCALE_XYZ 8388608    // 512*512*32
#define SCALE_YZ  16384      // 512*32
#define SCALE_Z   32
#define TOTAL_CELLS 33554432 // 4 * SCALE_XYZ
#define NWORDS (TOTAL_CELLS / 32)   // 1,048,576 bitmap words
#define NBLK_SCAN 1024       // NWORDS / (256 thr * 4 words)
#define NBLK_CSCAN 1024      // >= ceil(NPTS/1024)

// ---------------- scratch (device globals; no allocation allowed) -------------
__device__ unsigned int g_bits[NWORDS];        // occupancy bitmap (memset 0)
__device__ int   g_wpfx[NWORDS];               // exclusive rank prefix per word
__device__ int   g_code[NPTS];
__device__ int   g_inv[NPTS];
__device__ int   g_unq[NPTS];                  // memset 0xFF => -1 padding
__device__ int   g_icnt[NPTS];                 // per-segment counts (memset 0)
__device__ int   g_off[NPTS + 1];              // CSR offsets
__device__ int   g_cur[NPTS];                  // scatter cursors
__device__ int   g_pts[NPTS];                  // points grouped by segment
__device__ int   g_bsum[NBLK_SCAN];
__device__ int   g_bsum2[NBLK_CSCAN];

// ---------------- stage 1: voxel code + occupancy bit ------------------------
__global__ void k_code(const float* __restrict__ mu, const int* __restrict__ bidx, int n) {
    int i = blockIdx.x * blockDim.x + threadIdx.x;
    if (i >= n) return;
    float x = mu[i*3+0], y = mu[i*3+1], z = mu[i*3+2];
    // must match XLA exactly: (mu - pc_min) / vox with IEEE div, floor, int32 cast
    int ix = (int)floorf(__fdiv_rn(x - (-51.2f), 0.2f));
    int iy = (int)floorf(__fdiv_rn(y - (-51.2f), 0.2f));
    int iz = (int)floorf(__fdiv_rn(z - (-3.2f),  0.2f));
    int code = bidx[i] * SCALE_XYZ + iz * SCALE_YZ + iy * SCALE_Z + ix;
    g_code[i] = code;
    atomicOr(&g_bits[code >> 5], 1u << (code & 31));
}

// ---------------- stage 2a: per-block popcount sums (128 bits / thread) ------
__global__ void k_pass1() {
    uint4 v = ((const uint4*)g_bits)[blockIdx.x * 256 + threadIdx.x];
    int s = __popc(v.x) + __popc(v.y) + __popc(v.z) + __popc(v.w);
    __shared__ int sh[256];
    sh[threadIdx.x] = s; __syncthreads();
    for (int o = 128; o > 0; o >>= 1) {
        if (threadIdx.x < o) sh[threadIdx.x] += sh[threadIdx.x + o];
        __syncthreads();
    }
    if (threadIdx.x == 0) g_bsum[blockIdx.x] = sh[0];
}

// ---------------- stage 2b: single-block scan of 1024 block sums -------------
__global__ void k_scanb() {
    __shared__ int sh[1024];
    int t = threadIdx.x;
    int v = g_bsum[t];
    sh[t] = v; __syncthreads();
    for (int o = 1; o < 1024; o <<= 1) {
        int val = (t >= o) ? sh[t - o] : 0;
        __syncthreads();
        sh[t] += val;
        __syncthreads();
    }
    g_bsum[t] = sh[t] - v;   // exclusive
}

// ---------------- stage 2c: word prefixes + sorted unique codes --------------
__global__ void k_pass3() {
    __shared__ int sh[256];
    int t = threadIdx.x;
    uint4 v = ((const uint4*)g_bits)[blockIdx.x * 256 + t];
    int c0 = __popc(v.x), c1 = __popc(v.y), c2 = __popc(v.z), c3 = __popc(v.w);
    int s = c0 + c1 + c2 + c3;
    sh[t] = s; __syncthreads();
    for (int o = 1; o < 256; o <<= 1) {
        int val = (t >= o) ? sh[t - o] : 0;
        __syncthreads();
        sh[t] += val;
        __syncthreads();
    }
    int run = g_bsum[blockIdx.x] + ((t == 0) ? 0 : sh[t - 1]);
    int wbase = blockIdx.x * 1024 + t * 4;
    unsigned int w[4] = { v.x, v.y, v.z, v.w };
    int cnt[4] = { c0, c1, c2, c3 };
    #pragma unroll
    for (int j = 0; j < 4; j++) {
        g_wpfx[wbase + j] = run;                 // dense coalesced write
        unsigned int m = w[j];
        int cellbase = (wbase + j) << 5;
        int rr = run;
        while (m) {                              // emit set bits LSB->MSB (ascending cell)
            int b = __ffs(m) - 1;
            m &= m - 1;
            g_unq[rr++] = cellbase + b;
        }
        run += cnt[j];
    }
}

// ---------------- stage 3: rank via popc + segment counts --------------------
__global__ void k_inv(int n) {
    int i = blockIdx.x * blockDim.x + threadIdx.x;
    if (i >= n) return;
    int code = g_code[i];
    unsigned int w = g_bits[code >> 5];          // L2-resident 4MB
    int s = g_wpfx[code >> 5]                    // L2-resident 4MB
          + __popc(w & ((1u << (code & 31)) - 1u));
    g_inv[i] = s;
    atomicAdd(&g_icnt[s], 1);
}

// ---------------- stage 3b: scan counts (3 sub-kernels) ----------------------
__global__ void k_cs1(int n) {
    int t = threadIdx.x;
    int base = blockIdx.x * 1024 + t * 4;
    int s = 0;
    if (base < n) {   // n % 4 == 0 so int4 load is safe when base < n
        int4 v = *(const int4*)&g_icnt[base];
        s = v.x + v.y + v.z + v.w;
    }
    __shared__ int sh[256];
    sh[t] = s; __syncthreads();
    for (int o = 128; o > 0; o >>= 1) {
        if (t < o) sh[t] += sh[t + o];
        __syncthreads();
    }
    if (t == 0) g_bsum2[blockIdx.x] = sh[0];
}

__global__ void k_cs2(int nblk) {
    __shared__ int sh[NBLK_CSCAN];
    int t = threadIdx.x;
    int v = (t < nblk) ? g_bsum2[t] : 0;
    sh[t] = v; __syncthreads();
    for (int o = 1; o < NBLK_CSCAN; o <<= 1) {
        int val = (t >= o) ? sh[t - o] : 0;
        __syncthreads();
        sh[t] += val;
        __syncthreads();
    }
    g_bsum2[t] = (t == 0) ? 0 : sh[t - 1];   // exclusive
}

__global__ void k_cs3(int n) {
    __shared__ int sh[256];
    int t = threadIdx.x;
    int base = blockIdx.x * 1024 + t * 4;
    int4 v = make_int4(0, 0, 0, 0);
    if (base < n) v = *(const int4*)&g_icnt[base];
    int s = v.x + v.y + v.z + v.w;
    sh[t] = s; __syncthreads();
    for (int o = 1; o < 256; o <<= 1) {
        int val = (t >= o) ? sh[t - o] : 0;
        __syncthreads();
        sh[t] += val;
        __syncthreads();
    }
    int run = g_bsum2[blockIdx.x] + ((t == 0) ? 0 : sh[t - 1]);
    if (base < n) {
        int e[4] = { v.x, v.y, v.z, v.w };
        #pragma unroll
        for (int j = 0; j < 4; j++) {
            g_off[base + j] = run;
            g_cur[base + j] = run;
            run += e[j];
            if (base + j == n - 1) g_off[n] = run;
        }
    }
}

// ---------------- stage 3c: scatter points into segment lists ----------------
__global__ void k_scatter(int n) {
    int i = blockIdx.x * blockDim.x + threadIdx.x;
    if (i >= n) return;
    int s = g_inv[i];
    int pos = atomicAdd(&g_cur[s], 1);
    g_pts[pos] = i;
}

// ---------------- stage 4: warp-per-row gather reduce + write ----------------
// lane map: 0-2 mu | 3 dummy(rot w) | 4-7 rot | 8-10 scale | 11-26 sem | 27 vox
// all lanes: ft channels (2*lane, 2*lane+1) via float2
__global__ void k_reduce(const float* __restrict__ mu, const float* __restrict__ sc,
                         const float* __restrict__ rot, const float* __restrict__ ft,
                         const float* __restrict__ sm, float* __restrict__ out, int n) {
    int gtid = blockIdx.x * blockDim.x + threadIdx.x;
    int r = gtid >> 5;
    int lane = gtid & 31;
    if (r >= n) return;

    int start = g_off[r];
    int end   = g_off[r + 1];
    int c     = end - start;

    // per-lane gather descriptor (uniform over loop)
    const float* gbase; int gstride, gsub;
    if (lane < 3)       { gbase = mu;  gstride = 3;  gsub = lane; }
    else if (lane < 8)  { gbase = rot; gstride = 4;  gsub = (lane - 4) & 3; }
    else if (lane < 11) { gbase = sc;  gstride = 3;  gsub = lane - 8; }
    else if (lane < 27) { gbase = sm;  gstride = 16; gsub = lane - 11; }
    else                { gbase = mu;  gstride = 0;  gsub = 0; }
    bool isrot = (lane >= 4 && lane < 8);

    const float2* ft2 = (const float2*)ft;
    float a0 = 0.f, a1 = 0.f, am = 0.f;

    if (c == 1) {
        // singleton fast path: ref = self, dot = |q|^2 >= 0 -> sign always +1
        int i = g_pts[start];
        float2 f = __ldcs(&ft2[(size_t)i*32 + lane]);
        a0 = f.x; a1 = f.y;
        am = __ldg(&gbase[(size_t)i*gstride + gsub]);
    } else if (c > 1) {
        // first-occurrence reference = min point index
        int mn = INT_MAX;
        for (int j = start + lane; j < end; j += 32) mn = min(mn, g_pts[j]);
        mn = __reduce_min_sync(0xffffffffu, mn);
        float qc = 0.f;
        if (isrot) qc = __ldg(&rot[(size_t)mn*4 + (lane - 4)]);
        for (int j = start; j < end; j++) {
            int i = g_pts[j];                                  // broadcast load
            float2 f = __ldcs(&ft2[(size_t)i*32 + lane]);
            a0 += f.x; a1 += f.y;
            float v = __ldg(&gbase[(size_t)i*gstride + gsub]); // one converged gather
            if (isrot) {
                float p = v * qc;
                p += __shfl_xor_sync(0x000000F0u, p, 1);
                p += __shfl_xor_sync(0x000000F0u, p, 2);       // full dot in quad
                float sg = (p + 1e-8f) >= 0.f ? 1.f : -1.f;
                v *= sg;
            }
            am += v;
        }
    }
    // c == 0: padded segment, all zeros

    float inv_d = 1.0f / fmaxf((float)c, 1.0f);

    float*  out_mu  = out;
    float*  out_sc  = out + 3  * (size_t)n;
    float*  out_rot = out + 6  * (size_t)n;
    float2* out_ft2 = (float2*)(out + 10 * (size_t)n);
    float*  out_sm  = out + 74 * (size_t)n;
    float*  out_vx  = out + 90 * (size_t)n;

    __stcs(&out_ft2[(size_t)r*32 + lane], make_float2(a0 * inv_d, a1 * inv_d));

    if (lane < 3) {
        out_mu[(size_t)r*3 + lane] = am * inv_d;
    } else if (isrot) {
        float p = am * inv_d;
        float v = p * p;
        v += __shfl_xor_sync(0x000000F0u, v, 1);
        v += __shfl_xor_sync(0x000000F0u, v, 2);
        float nrm = sqrtf(v);
        out_rot[(size_t)r*4 + (lane - 4)] = p / fmaxf(nrm, 1e-12f);
    } else if (lane >= 8 && lane < 11) {
        out_sc[(size_t)r*3 + (lane - 8)] = am * inv_d;
    } else if (lane >= 11 && lane < 27) {
        out_sm[(size_t)r*NS + (lane - 11)] = am * inv_d;
    } else if (lane == 27) {
        int u = g_unq[r];
        int vb, vz, vy, vx;
        if (u < 0) { vb = -1; vz = 511; vy = 511; vx = 31; }  // jnp floor-div/mod of -1
        else {
            vb = u / SCALE_XYZ; int rem = u % SCALE_XYZ;
            vz = rem / SCALE_YZ; rem %= SCALE_YZ;
            vy = rem / SCALE_Z;  vx = rem % SCALE_Z;
        }
        float* vo = out_vx + (size_t)r * 4;
        vo[0] = (float)vb; vo[1] = (float)vz; vo[2] = (float)vy; vo[3] = (float)vx;
    }
}

// -----------------------------------------------------------------------------
extern "C" void kernel_launch(void* const* d_in, const int* in_sizes, int n_in,
                              void* d_out, int out_size) {
    const float* mu   = (const float*)d_in[0];
    const float* sc   = (const float*)d_in[1];
    const float* rot  = (const float*)d_in[2];
    const float* ft   = (const float*)d_in[3];
    const float* sm   = (const float*)d_in[4];
    const int*   bidx = (const int*)  d_in[5];
    float* out = (float*)d_out;
    int n = in_sizes[5];   // batch_idx element count == N

    void *p_bits, *p_unq, *p_icnt;
    cudaGetSymbolAddress(&p_bits, g_bits);
    cudaGetSymbolAddress(&p_unq, g_unq);
    cudaGetSymbolAddress(&p_icnt, g_icnt);

    cudaMemsetAsync(p_bits, 0x00, (size_t)NWORDS * sizeof(unsigned int)); // 4MB
    cudaMemsetAsync(p_unq,  0xFF, (size_t)n * sizeof(int));               // -1 padding
    cudaMemsetAsync(p_icnt, 0x00, (size_t)n * sizeof(int));               // counts

    int tb = 256;
    int pblk = (n + tb - 1) / tb;
    int cblk = (n + 1023) / 1024;

    k_code   <<<pblk, tb>>>(mu, bidx, n);
    k_pass1  <<<NBLK_SCAN, tb>>>();
    k_scanb  <<<1, 1024>>>();
    k_pass3  <<<NBLK_SCAN, tb>>>();
    k_inv    <<<pblk, tb>>>(n);
    k_cs1    <<<cblk, tb>>>(n);
    k_cs2    <<<1, NBLK_CSCAN>>>(cblk);
    k_cs3    <<<cblk, tb>>>(n);
    k_scatter<<<pblk, tb>>>(n);

    long long wthreads = (long long)n * 32;
    int wblocks = (int)((wthreads + tb - 1) / tb);
    k_reduce <<<wblocks, tb>>>(mu, sc, rot, ft, sm, out, n);
}